// round 2
// baseline (speedup 1.0000x reference)
#include <cuda_runtime.h>
#include <math.h>

// ---------------------------------------------------------------------------
// KnotAttention: out[n, h*32+v] = sum_r softmax_over_n(Q.K/sqrt(32))[h,n,r] * V[h,n,r,v]
// Q = x @ Wq[h];  K/V[r] = x_nb[:,r,:] @ Wk/Wv[h,r]   (r=0 is self, r=1..4 gathered)
// Softmax is over the NODE axis per (h,r): denom = sum_n exp(logit[h,n,r]).
// NOTE: neighbor_index may be int32 (JAX x64 disabled) or int64 -> runtime detect.
// ---------------------------------------------------------------------------

#define TN 64                  // nodes per block
#define MAXN 131072
#define MAX_NB ((MAXN + TN - 1) / TN)

// scratch (allocation-free rule: __device__ globals)
__device__ float g_V[(size_t)MAXN * 5 * 128];   // V[n][r][h*32+v]
__device__ float g_E[(size_t)20 * MAXN];        // exp(logit)[(h*5+r)][n]
__device__ float g_part[(size_t)20 * MAX_NB];   // per-block partial sums
__device__ float g_Sinv[20];                    // 1/denominator
__device__ int   g_is64;                        // 1 if neighbor_index is int64

// Detect index dtype: int64 values < 2^31 have all-zero high words at odd
// int32 positions; genuine int32 random indices in [0,N) make that
// essentially impossible across 32 samples.
__global__ void knot_detect(const int* __restrict__ nbr_i32)
{
    if (threadIdx.x == 0 && blockIdx.x == 0) {
        int any = 0;
        #pragma unroll
        for (int i = 1; i < 64; i += 2) any |= nbr_i32[i];
        g_is64 = (any == 0) ? 1 : 0;
    }
}

__global__ __launch_bounds__(256, 2)
void knot_k1(const float* __restrict__ x, const void* __restrict__ nbr,
             const float* __restrict__ wq, const float* __restrict__ wk,
             const float* __restrict__ wv, int N)
{
    __shared__ float xs[TN * 132];     // 64 rows, stride 132 floats (33792 B)
    __shared__ float wpart[8][4];      // per-warp per-head partial exp sums

    const int t  = threadIdx.x;
    const int w  = t >> 5;             // warp 0..7
    const int l  = t & 31;             // lane == k index
    const int n0 = blockIdx.x * TN;
    const int NB = gridDim.x;
    const int is64 = g_is64;

    // Q accumulators persist across r loop. Thread owns nodes {w+8i}, head j, k=l.
    float Qacc[8][4];
    #pragma unroll
    for (int i = 0; i < 8; ++i)
        #pragma unroll
        for (int j = 0; j < 4; ++j) Qacc[i][j] = 0.0f;

    for (int r = 0; r < 5; ++r) {
        __syncthreads();
        // ---- stage 64 (possibly gathered) x rows into smem, fully coalesced ----
        #pragma unroll
        for (int i = 0; i < 8; ++i) {
            int f   = t + 256 * i;         // 0..2047 float4 slots
            int row = f >> 5;              // 0..63
            int seg = f & 31;              // float4 within row
            int n   = n0 + row;
            int nc  = (n < N) ? n : 0;
            long long src;
            if (r == 0) {
                src = (long long)nc;
            } else {
                long long e = (long long)nc * 4 + (r - 1);
                src = is64 ? __ldg((const long long*)nbr + e)
                           : (long long)__ldg((const int*)nbr + e);
            }
            if (src < 0) src = 0;
            if (src >= N) src = N - 1;
            float4 v = __ldg((const float4*)(x + (size_t)src * 128 + seg * 4));
            *(float4*)(xs + row * 132 + seg * 4) = v;
        }
        __syncthreads();

        // ---- Q GEMM (r==0 only): Qacc[i][j] = sum_d xs[node][d] * wq[j][d][l] ----
        if (r == 0) {
            #pragma unroll 4
            for (int d = 0; d < 128; ++d) {
                float xv[8];
                #pragma unroll
                for (int i = 0; i < 8; ++i) xv[i] = xs[(w + 8 * i) * 132 + d];
                #pragma unroll
                for (int j = 0; j < 4; ++j) {
                    float wvv = __ldg(wq + ((size_t)j * 128 + d) * 32 + l);
                    #pragma unroll
                    for (int i = 0; i < 8; ++i) Qacc[i][j] = fmaf(xv[i], wvv, Qacc[i][j]);
                }
            }
        }

        // ---- K GEMM ----
        float Kacc[8][4];
        #pragma unroll
        for (int i = 0; i < 8; ++i)
            #pragma unroll
            for (int j = 0; j < 4; ++j) Kacc[i][j] = 0.0f;

        #pragma unroll 4
        for (int d = 0; d < 128; ++d) {
            float xv[8];
            #pragma unroll
            for (int i = 0; i < 8; ++i) xv[i] = xs[(w + 8 * i) * 132 + d];
            #pragma unroll
            for (int j = 0; j < 4; ++j) {
                float wvv = __ldg(wk + (((size_t)(j * 5 + r) * 128 + d) * 32) + l);
                #pragma unroll
                for (int i = 0; i < 8; ++i) Kacc[i][j] = fmaf(xv[i], wvv, Kacc[i][j]);
            }
        }

        // ---- logits: dot over k (==lane) via warp butterfly; exp; partial sums ----
        float hsum0 = 0.f, hsum1 = 0.f, hsum2 = 0.f, hsum3 = 0.f;
        #pragma unroll
        for (int i = 0; i < 8; ++i) {
            int n = n0 + w + 8 * i;
            #pragma unroll
            for (int j = 0; j < 4; ++j) {
                float p = Qacc[i][j] * Kacc[i][j];
                p += __shfl_xor_sync(0xFFFFFFFFu, p, 16);
                p += __shfl_xor_sync(0xFFFFFFFFu, p, 8);
                p += __shfl_xor_sync(0xFFFFFFFFu, p, 4);
                p += __shfl_xor_sync(0xFFFFFFFFu, p, 2);
                p += __shfl_xor_sync(0xFFFFFFFFu, p, 1);
                if (l == 0) {
                    float e = 0.0f;
                    if (n < N) {
                        e = expf(p * 0.17677669529663687f);   // 1/sqrt(32)
                        g_E[(size_t)(j * 5 + r) * N + n] = e;
                    }
                    if (j == 0) hsum0 += e;
                    else if (j == 1) hsum1 += e;
                    else if (j == 2) hsum2 += e;
                    else hsum3 += e;
                }
            }
        }
        if (l == 0) {
            wpart[w][0] = hsum0; wpart[w][1] = hsum1;
            wpart[w][2] = hsum2; wpart[w][3] = hsum3;
        }
        __syncthreads();
        if (t < 4) {
            float s = 0.f;
            #pragma unroll
            for (int ww = 0; ww < 8; ++ww) s += wpart[ww][t];
            g_part[(size_t)(t * 5 + r) * NB + blockIdx.x] = s;
        }

        // ---- V GEMM + store to scratch ----
        float Vacc[8][4];
        #pragma unroll
        for (int i = 0; i < 8; ++i)
            #pragma unroll
            for (int j = 0; j < 4; ++j) Vacc[i][j] = 0.0f;

        #pragma unroll 4
        for (int d = 0; d < 128; ++d) {
            float xv[8];
            #pragma unroll
            for (int i = 0; i < 8; ++i) xv[i] = xs[(w + 8 * i) * 132 + d];
            #pragma unroll
            for (int j = 0; j < 4; ++j) {
                float wvv = __ldg(wv + (((size_t)(j * 5 + r) * 128 + d) * 32) + l);
                #pragma unroll
                for (int i = 0; i < 8; ++i) Vacc[i][j] = fmaf(xv[i], wvv, Vacc[i][j]);
            }
        }
        #pragma unroll
        for (int i = 0; i < 8; ++i) {
            int n = n0 + w + 8 * i;
            if (n < N) {
                #pragma unroll
                for (int j = 0; j < 4; ++j)
                    g_V[((size_t)n * 5 + r) * 128 + 32 * j + l] = Vacc[i][j];
            }
        }
    }
}

// deterministic reduction of per-block partials -> 1/denominator
__global__ void knot_k2(int NB)
{
    __shared__ float sm[256];
    const int b = blockIdx.x;         // 0..19 = (h*5+r)
    float s = 0.f;
    for (int i = threadIdx.x; i < NB; i += 256)
        s += g_part[(size_t)b * NB + i];
    sm[threadIdx.x] = s;
    __syncthreads();
    for (int off = 128; off > 0; off >>= 1) {
        if (threadIdx.x < off) sm[threadIdx.x] += sm[threadIdx.x + off];
        __syncthreads();
    }
    if (threadIdx.x == 0) g_Sinv[b] = 1.0f / sm[0];
}

// epilogue: out[n, c] = sum_r (E/S) * V
__global__ void knot_k3(float* __restrict__ out, int N)
{
    int idx = blockIdx.x * 256 + threadIdx.x;
    if (idx >= N * 128) return;
    int c = idx & 127;
    int n = idx >> 7;
    int h = c >> 5;
    float acc = 0.f;
    #pragma unroll
    for (int r = 0; r < 5; ++r) {
        float e  = __ldg(&g_E[(size_t)(h * 5 + r) * N + n]);
        float si = g_Sinv[h * 5 + r];
        float v  = __ldg(&g_V[((size_t)n * 5 + r) * 128 + c]);
        acc = fmaf(e * si, v, acc);
    }
    out[idx] = acc;
}

extern "C" void kernel_launch(void* const* d_in, const int* in_sizes, int n_in,
                              void* d_out, int out_size)
{
    const float* x   = (const float*)d_in[0];
    const void*  nbr = d_in[1];
    const float* wq  = (const float*)d_in[2];
    const float* wk  = (const float*)d_in[3];
    const float* wv  = (const float*)d_in[4];
    float*       out = (float*)d_out;

    const int N  = in_sizes[0] / 128;
    const int NB = (N + TN - 1) / TN;

    knot_detect<<<1, 32>>>((const int*)nbr);
    knot_k1<<<NB, 256>>>(x, nbr, wq, wk, wv, N);
    knot_k2<<<20, 256>>>(NB);
    knot_k3<<<(N * 128 + 255) / 256, 256>>>(out, N);
}

// round 4
// speedup vs baseline: 4.1041x; 4.1041x over previous
#include <cuda_runtime.h>
#include <math.h>
#include <stdint.h>

// ===========================================================================
// KnotAttention via mma.sync tf32 (sm_103-portable HMMA path).
//  prep: transpose weights to [n=h*32+k][d], rounded to tf32 (11 x 64KB images)
//  E:    per 128-node tile: Q=A0@Wq; per r: K_r=A_r@Wk_r; E=exp(QK/sqrt32), partials
//  R:    reduce partials -> 1/denominator  (softmax over NODE axis)
//  O:    per r: V_r=A_r@Wv_r; acc += (E*Sinv)*V_r; write out
// ===========================================================================

#define NT       128
#define THREADS  256
#define MAXN     131072
#define MAXTILES (MAXN / NT)
#define SCALE    0.17677669529663687f   // 1/sqrt(32)
#define AS       132                    // smem row stride (floats), conflict-free
#define W_OFF    (128 * AS)             // W region offset in floats
#define SMEM_SZ  (2 * 128 * AS * 4)     // 135168 bytes

__device__ float g_E[(size_t)20 * MAXN];
__device__ float g_part[20 * MAXTILES];
__device__ float g_Sinv[20];
__device__ int   g_is64;
__device__ float g_Wt[11 * 128 * 128];  // [slot][n][d], tf32-rounded

// -------- helpers --------
__device__ __forceinline__ uint32_t smem_u32(const void* p) {
    uint32_t a;
    asm("{ .reg .u64 t; cvta.to.shared.u64 t, %1; cvt.u32.u64 %0, t; }" : "=r"(a) : "l"(p));
    return a;
}
__device__ __forceinline__ void cpa16(uint32_t s, const void* g) {
    asm volatile("cp.async.cg.shared.global [%0], [%1], 16;" :: "r"(s), "l"(g) : "memory");
}
__device__ __forceinline__ void cpa_waitall() {
    asm volatile("cp.async.commit_group;\ncp.async.wait_group 0;" ::: "memory");
}
__device__ __forceinline__ uint32_t f2tf(float x) {
    uint32_t u;
    asm("cvt.rna.tf32.f32 %0, %1;" : "=r"(u) : "f"(x));
    return u;
}
__device__ __forceinline__ void mma8(float* c, uint32_t a0, uint32_t a1, uint32_t a2,
                                     uint32_t a3, uint32_t b0, uint32_t b1) {
    asm volatile(
        "mma.sync.aligned.m16n8k8.row.col.f32.tf32.tf32.f32 "
        "{%0,%1,%2,%3}, {%4,%5,%6,%7}, {%8,%9}, {%0,%1,%2,%3};"
        : "+f"(c[0]), "+f"(c[1]), "+f"(c[2]), "+f"(c[3])
        : "r"(a0), "r"(a1), "r"(a2), "r"(a3), "r"(b0), "r"(b1));
}

// -------- prep: weight images [slot][n][d], tf32-rounded --------
__global__ void knot_prep(const float* __restrict__ wq, const float* __restrict__ wk,
                          const float* __restrict__ wv)
{
    int slot = blockIdx.x;
    float* dst = g_Wt + slot * 16384;
    for (int i = 0; i < 64; ++i) {
        int f = threadIdx.x + 256 * i;     // 0..16383
        int n = f >> 7, d = f & 127;
        int h = n >> 5, k = n & 31;
        float v;
        if (slot == 0)      v = wq[((size_t)h * 128 + d) * 32 + k];
        else if (slot <= 5) v = wk[(((size_t)(h * 5 + (slot - 1)) * 128) + d) * 32 + k];
        else                v = wv[(((size_t)(h * 5 + (slot - 6)) * 128) + d) * 32 + k];
        dst[f] = __uint_as_float(f2tf(v));
    }
}

__global__ void knot_detect(const int* __restrict__ nbr_i32)
{
    if (threadIdx.x == 0 && blockIdx.x == 0) {
        int any = 0;
        #pragma unroll
        for (int i = 1; i < 64; i += 2) any |= nbr_i32[i];
        g_is64 = (any == 0) ? 1 : 0;
    }
}

// -------- staging (row-major, stride AS) --------
__device__ __forceinline__ void stage_A(float* sA, const float* __restrict__ x,
                                        const void* __restrict__ nbr, int is64,
                                        int n0, int r, int N)
{
    int t = threadIdx.x;
    #pragma unroll
    for (int i = 0; i < 16; ++i) {
        int f = t + 256 * i;               // 4096 chunks of 16B
        int row = f >> 5, c4 = f & 31;
        int n = n0 + row;
        int nc = (n < N) ? n : 0;
        long long src;
        if (r == 0) src = nc;
        else {
            long long e = (long long)nc * 4 + (r - 1);
            src = is64 ? __ldg((const long long*)nbr + e)
                       : (long long)__ldg((const int*)nbr + e);
        }
        if (src < 0) src = 0;
        if (src >= N) src = N - 1;
        cpa16(smem_u32(sA + row * AS + c4 * 4), x + (size_t)src * 128 + c4 * 4);
    }
}
__device__ __forceinline__ void stage_W(float* sW, int slot)
{
    const float* src = g_Wt + slot * 16384;
    int t = threadIdx.x;
    #pragma unroll
    for (int i = 0; i < 16; ++i) {
        int f = t + 256 * i;
        int row = f >> 5, c4 = f & 31;
        cpa16(smem_u32(sW + row * AS + c4 * 4), src + f * 4);
    }
}

// -------- warp GEMM: C[2][8][4] += A(128x128) @ W^T (per-warp 32x64 block) -----
// warp wm (0..3) owns rows wm*32..wm*32+31; wn (0..1) owns cols wn*64..wn*64+63.
__device__ __forceinline__ void gemm128(const float* sA, const float* sW,
                                        int wm, int wn, int g, int t4,
                                        float C[2][8][4])
{
    #pragma unroll
    for (int ks = 0; ks < 16; ++ks) {
        uint32_t a[2][4];
        #pragma unroll
        for (int mt = 0; mt < 2; ++mt) {
            const float* ap = sA + (wm * 32 + mt * 16 + g) * AS + ks * 8 + t4;
            a[mt][0] = f2tf(ap[0]);
            a[mt][1] = f2tf(ap[8 * AS]);
            a[mt][2] = f2tf(ap[4]);
            a[mt][3] = f2tf(ap[8 * AS + 4]);
        }
        #pragma unroll
        for (int nt = 0; nt < 8; ++nt) {
            const float* bp = sW + (wn * 64 + nt * 8 + g) * AS + ks * 8 + t4;
            uint32_t b0 = __float_as_uint(bp[0]);
            uint32_t b1 = __float_as_uint(bp[4]);
            mma8(C[0][nt], a[0][0], a[0][1], a[0][2], a[0][3], b0, b1);
            mma8(C[1][nt], a[1][0], a[1][1], a[1][2], a[1][3], b0, b1);
        }
    }
}

// -------- kernel E --------
__global__ __launch_bounds__(THREADS, 1)
void knot_E(const float* __restrict__ x, const void* __restrict__ nbr, int N)
{
    extern __shared__ float smf[];
    float* sA = smf;
    float* sW = smf + W_OFF;
    __shared__ float warr[8][2];

    const int t = threadIdx.x, w = t >> 5, l = t & 31;
    const int wm = w >> 1, wn = w & 1, g = l >> 2, t4 = l & 3;
    const int tile = blockIdx.x, n0 = tile * NT;
    const int is64 = g_is64;

    stage_W(sW, 0);
    stage_A(sA, x, nbr, is64, n0, 0, N);
    cpa_waitall();
    __syncthreads();

    float qC[2][8][4];
    #pragma unroll
    for (int mt = 0; mt < 2; ++mt)
        #pragma unroll
        for (int nt = 0; nt < 8; ++nt)
            #pragma unroll
            for (int ci = 0; ci < 4; ++ci) qC[mt][nt][ci] = 0.f;
    gemm128(sA, sW, wm, wn, g, t4, qC);
    __syncthreads();            // all warps done with sW before restage

    for (int r = 0; r < 5; ++r) {
        stage_W(sW, 1 + r);
        if (r > 0) stage_A(sA, x, nbr, is64, n0, r, N);
        cpa_waitall();
        __syncthreads();

        float kC[2][8][4];
        #pragma unroll
        for (int mt = 0; mt < 2; ++mt)
            #pragma unroll
            for (int nt = 0; nt < 8; ++nt)
                #pragma unroll
                for (int ci = 0; ci < 4; ++ci) kC[mt][nt][ci] = 0.f;
        gemm128(sA, sW, wm, wn, g, t4, kC);

        // ---- logits, exp, E store, partial sums ----
        float hs0 = 0.f, hs1 = 0.f;
        #pragma unroll
        for (int mt = 0; mt < 2; ++mt) {
            #pragma unroll
            for (int rr = 0; rr < 2; ++rr) {
                int n = n0 + wm * 32 + mt * 16 + g + rr * 8;
                #pragma unroll
                for (int hl = 0; hl < 2; ++hl) {
                    float ds = 0.f;
                    #pragma unroll
                    for (int nt4 = 0; nt4 < 4; ++nt4) {
                        int nt = hl * 4 + nt4;
                        ds = fmaf(qC[mt][nt][rr * 2],     kC[mt][nt][rr * 2],     ds);
                        ds = fmaf(qC[mt][nt][rr * 2 + 1], kC[mt][nt][rr * 2 + 1], ds);
                    }
                    ds += __shfl_xor_sync(0xFFFFFFFFu, ds, 1);
                    ds += __shfl_xor_sync(0xFFFFFFFFu, ds, 2);
                    if (t4 == 0) {
                        float e = 0.f;
                        if (n < N) {
                            e = expf(ds * SCALE);
                            g_E[(size_t)((wn * 2 + hl) * 5 + r) * N + n] = e;
                        }
                        if (hl == 0) hs0 += e; else hs1 += e;
                    }
                }
            }
        }
        #pragma unroll
        for (int o = 16; o > 0; o >>= 1) {
            hs0 += __shfl_down_sync(0xFFFFFFFFu, hs0, o);
            hs1 += __shfl_down_sync(0xFFFFFFFFu, hs1, o);
        }
        if (l == 0) { warr[w][0] = hs0; warr[w][1] = hs1; }
        __syncthreads();        // also guarantees GEMM smem reads done
        if (t < 4) {
            int h = t;
            float s = 0.f;
            #pragma unroll
            for (int m = 0; m < 4; ++m) s += warr[m * 2 + (h >> 1)][h & 1];
            g_part[(h * 5 + r) * MAXTILES + tile] = s;
        }
    }
}

// -------- kernel R --------
__global__ void knot_R(int cnt)
{
    __shared__ float smr[256];
    const int b = blockIdx.x;
    float s = 0.f;
    for (int i = threadIdx.x; i < cnt; i += 256) s += g_part[b * MAXTILES + i];
    smr[threadIdx.x] = s;
    __syncthreads();
    for (int off = 128; off > 0; off >>= 1) {
        if (threadIdx.x < off) smr[threadIdx.x] += smr[threadIdx.x + off];
        __syncthreads();
    }
    if (threadIdx.x == 0) g_Sinv[b] = 1.0f / smr[0];
}

// -------- kernel O --------
__global__ __launch_bounds__(THREADS, 1)
void knot_O(const float* __restrict__ x, const void* __restrict__ nbr,
            float* __restrict__ out, int N)
{
    extern __shared__ float smf[];
    float* sA = smf;
    float* sW = smf + W_OFF;

    const int t = threadIdx.x, w = t >> 5, l = t & 31;
    const int wm = w >> 1, wn = w & 1, g = l >> 2, t4 = l & 3;
    const int tile = blockIdx.x, n0 = tile * NT;
    const int is64 = g_is64;

    float acc[2][8][4];
    #pragma unroll
    for (int mt = 0; mt < 2; ++mt)
        #pragma unroll
        for (int nt = 0; nt < 8; ++nt)
            #pragma unroll
            for (int ci = 0; ci < 4; ++ci) acc[mt][nt][ci] = 0.f;

    for (int r = 0; r < 5; ++r) {
        stage_W(sW, 6 + r);
        stage_A(sA, x, nbr, is64, n0, r, N);
        cpa_waitall();
        __syncthreads();

        float C[2][8][4];
        #pragma unroll
        for (int mt = 0; mt < 2; ++mt)
            #pragma unroll
            for (int nt = 0; nt < 8; ++nt)
                #pragma unroll
                for (int ci = 0; ci < 4; ++ci) C[mt][nt][ci] = 0.f;
        gemm128(sA, sW, wm, wn, g, t4, C);

        float av[2][2][2];   // [mt][rr][hl]
        #pragma unroll
        for (int mt = 0; mt < 2; ++mt)
            #pragma unroll
            for (int rr = 0; rr < 2; ++rr) {
                int n = n0 + wm * 32 + mt * 16 + g + rr * 8;
                #pragma unroll
                for (int hl = 0; hl < 2; ++hl) {
                    int h = wn * 2 + hl;
                    av[mt][rr][hl] = (n < N)
                        ? __ldg(&g_E[(size_t)(h * 5 + r) * N + n]) * g_Sinv[h * 5 + r]
                        : 0.f;
                }
            }
        #pragma unroll
        for (int mt = 0; mt < 2; ++mt)
            #pragma unroll
            for (int nt = 0; nt < 8; ++nt)
                #pragma unroll
                for (int ci = 0; ci < 4; ++ci)
                    acc[mt][nt][ci] = fmaf(av[mt][ci >> 1][nt >> 2], C[mt][nt][ci],
                                           acc[mt][nt][ci]);
        __syncthreads();    // smem reads done before next restage / transpose
    }

    // ---- transpose via smem, coalesced output ----
    #pragma unroll
    for (int mt = 0; mt < 2; ++mt)
        #pragma unroll
        for (int nt = 0; nt < 8; ++nt)
            #pragma unroll
            for (int ci = 0; ci < 4; ++ci) {
                int row = wm * 32 + mt * 16 + g + (ci >> 1) * 8;
                int col = wn * 64 + nt * 8 + t4 * 2 + (ci & 1);
                sA[row * AS + col] = acc[mt][nt][ci];
            }
    __syncthreads();
    #pragma unroll
    for (int i = 0; i < 16; ++i) {
        int f = t + 256 * i;
        int row = f >> 5, c4 = f & 31;
        int n = n0 + row;
        if (n < N)
            *(float4*)(out + (size_t)n * 128 + c4 * 4) =
                *(const float4*)(sA + row * AS + c4 * 4);
    }
}

extern "C" void kernel_launch(void* const* d_in, const int* in_sizes, int n_in,
                              void* d_out, int out_size)
{
    const float* x   = (const float*)d_in[0];
    const void*  nbr = d_in[1];
    const float* wq  = (const float*)d_in[2];
    const float* wk  = (const float*)d_in[3];
    const float* wv  = (const float*)d_in[4];
    float*       out = (float*)d_out;

    const int N   = in_sizes[0] / 128;
    const int NBT = (N + NT - 1) / NT;

    cudaFuncSetAttribute(knot_E, cudaFuncAttributeMaxDynamicSharedMemorySize, SMEM_SZ);
    cudaFuncSetAttribute(knot_O, cudaFuncAttributeMaxDynamicSharedMemorySize, SMEM_SZ);

    knot_detect<<<1, 32>>>((const int*)nbr);
    knot_prep<<<11, 256>>>(wq, wk, wv);
    knot_E<<<NBT, THREADS, SMEM_SZ>>>(x, nbr, N);
    knot_R<<<20, 256>>>(NBT);
    knot_O<<<NBT, THREADS, SMEM_SZ>>>(x, nbr, out, N);
}

// round 5
// speedup vs baseline: 4.8725x; 1.1872x over previous
#include <cuda_runtime.h>
#include <math.h>
#include <stdint.h>

// ===========================================================================
// KnotAttention via mma.sync tf32, NT=64 tiles, 2 CTAs/SM for staging overlap.
//  prep: transpose weights to [n=h*32+k][d], tf32-rounded (11 x 64KB images)
//  E:    per 64-node tile: Q=A0@Wq; per r: K_r=A_r@Wk_r; E=exp(QK/sqrt32), partials
//  R:    reduce partials -> 1/denominator  (softmax over NODE axis)
//  O:    per r: V_r=A_r@Wv_r; acc += (E*Sinv)*V_r; write out
// ===========================================================================

#define NT       64
#define THREADS  256
#define MAXN     131072
#define MAXTILES (MAXN / NT)            // 2048
#define SCALE    0.17677669529663687f   // 1/sqrt(32)
#define AS       132                    // smem row stride (floats), conflict-free
#define W_OFF    (NT * AS)              // W region offset in floats (A = 64 rows)
#define SMEM_SZ  ((NT + 128) * AS * 4)  // 101376 bytes -> 2 CTAs/SM

__device__ float g_E[(size_t)20 * MAXN];
__device__ float g_part[20 * MAXTILES];
__device__ float g_Sinv[20];
__device__ int   g_is64;
__device__ float g_Wt[11 * 128 * 128];  // [slot][n][d], tf32-rounded

// -------- helpers --------
__device__ __forceinline__ uint32_t smem_u32(const void* p) {
    uint32_t a;
    asm("{ .reg .u64 t; cvta.to.shared.u64 t, %1; cvt.u32.u64 %0, t; }" : "=r"(a) : "l"(p));
    return a;
}
__device__ __forceinline__ void cpa16(uint32_t s, const void* g) {
    asm volatile("cp.async.cg.shared.global [%0], [%1], 16;" :: "r"(s), "l"(g) : "memory");
}
__device__ __forceinline__ void cpa_waitall() {
    asm volatile("cp.async.commit_group;\ncp.async.wait_group 0;" ::: "memory");
}
__device__ __forceinline__ uint32_t f2tf(float x) {
    uint32_t u;
    asm("cvt.rna.tf32.f32 %0, %1;" : "=r"(u) : "f"(x));
    return u;
}
__device__ __forceinline__ void mma8(float* c, uint32_t a0, uint32_t a1, uint32_t a2,
                                     uint32_t a3, uint32_t b0, uint32_t b1) {
    asm volatile(
        "mma.sync.aligned.m16n8k8.row.col.f32.tf32.tf32.f32 "
        "{%0,%1,%2,%3}, {%4,%5,%6,%7}, {%8,%9}, {%0,%1,%2,%3};"
        : "+f"(c[0]), "+f"(c[1]), "+f"(c[2]), "+f"(c[3])
        : "r"(a0), "r"(a1), "r"(a2), "r"(a3), "r"(b0), "r"(b1));
}

// -------- prep: weight images [slot][n][d], tf32-rounded --------
__global__ void knot_prep(const float* __restrict__ wq, const float* __restrict__ wk,
                          const float* __restrict__ wv)
{
    int slot = blockIdx.x;
    float* dst = g_Wt + slot * 16384;
    for (int i = 0; i < 64; ++i) {
        int f = threadIdx.x + 256 * i;     // 0..16383
        int n = f >> 7, d = f & 127;
        int h = n >> 5, k = n & 31;
        float v;
        if (slot == 0)      v = wq[((size_t)h * 128 + d) * 32 + k];
        else if (slot <= 5) v = wk[(((size_t)(h * 5 + (slot - 1)) * 128) + d) * 32 + k];
        else                v = wv[(((size_t)(h * 5 + (slot - 6)) * 128) + d) * 32 + k];
        dst[f] = __uint_as_float(f2tf(v));
    }
}

__global__ void knot_detect(const int* __restrict__ nbr_i32)
{
    if (threadIdx.x == 0 && blockIdx.x == 0) {
        int any = 0;
        #pragma unroll
        for (int i = 1; i < 64; i += 2) any |= nbr_i32[i];
        g_is64 = (any == 0) ? 1 : 0;
    }
}

// -------- staging (row-major, stride AS) --------
__device__ __forceinline__ void stage_A(float* sA, const float* __restrict__ x,
                                        const void* __restrict__ nbr, int is64,
                                        int n0, int r, int N)
{
    int t = threadIdx.x;
    #pragma unroll
    for (int i = 0; i < 8; ++i) {          // 64 rows x 32 chunks = 2048
        int f = t + 256 * i;
        int row = f >> 5, c4 = f & 31;
        int n = n0 + row;
        int nc = (n < N) ? n : 0;
        long long src;
        if (r == 0) src = nc;
        else {
            long long e = (long long)nc * 4 + (r - 1);
            src = is64 ? __ldg((const long long*)nbr + e)
                       : (long long)__ldg((const int*)nbr + e);
        }
        if (src < 0) src = 0;
        if (src >= N) src = N - 1;
        cpa16(smem_u32(sA + row * AS + c4 * 4), x + (size_t)src * 128 + c4 * 4);
    }
}
__device__ __forceinline__ void stage_W(float* sW, int slot)
{
    const float* src = g_Wt + slot * 16384;
    int t = threadIdx.x;
    #pragma unroll
    for (int i = 0; i < 16; ++i) {         // 128 rows x 32 chunks = 4096
        int f = t + 256 * i;
        int row = f >> 5, c4 = f & 31;
        cpa16(smem_u32(sW + row * AS + c4 * 4), src + f * 4);
    }
}

// -------- warp GEMM: per-warp 32x32 block of A(64x128) @ W^T --------
// wm (0..1): rows wm*32..+31 ; wn (0..3): cols wn*32..+31 (head wn)
__device__ __forceinline__ void gemm64(const float* sA, const float* sW,
                                       int wm, int wn, int g, int t4,
                                       float C[2][4][4])
{
    #pragma unroll
    for (int ks = 0; ks < 16; ++ks) {
        uint32_t a[2][4];
        #pragma unroll
        for (int mt = 0; mt < 2; ++mt) {
            const float* ap = sA + (wm * 32 + mt * 16 + g) * AS + ks * 8 + t4;
            a[mt][0] = f2tf(ap[0]);
            a[mt][1] = f2tf(ap[8 * AS]);
            a[mt][2] = f2tf(ap[4]);
            a[mt][3] = f2tf(ap[8 * AS + 4]);
        }
        #pragma unroll
        for (int nt = 0; nt < 4; ++nt) {
            const float* bp = sW + (wn * 32 + nt * 8 + g) * AS + ks * 8 + t4;
            uint32_t b0 = __float_as_uint(bp[0]);
            uint32_t b1 = __float_as_uint(bp[4]);
            mma8(C[0][nt], a[0][0], a[0][1], a[0][2], a[0][3], b0, b1);
            mma8(C[1][nt], a[1][0], a[1][1], a[1][2], a[1][3], b0, b1);
        }
    }
}

// -------- kernel E --------
__global__ __launch_bounds__(THREADS, 2)
void knot_E(const float* __restrict__ x, const void* __restrict__ nbr, int N)
{
    extern __shared__ float smf[];
    float* sA = smf;
    float* sW = smf + W_OFF;
    __shared__ float warr[8];

    const int t = threadIdx.x, w = t >> 5, l = t & 31;
    const int wm = w >> 2, wn = w & 3, g = l >> 2, t4 = l & 3;
    const int tile = blockIdx.x, n0 = tile * NT;
    const int is64 = g_is64;
    const int h = wn;

    stage_W(sW, 0);
    stage_A(sA, x, nbr, is64, n0, 0, N);
    cpa_waitall();
    __syncthreads();

    float qC[2][4][4];
    #pragma unroll
    for (int mt = 0; mt < 2; ++mt)
        #pragma unroll
        for (int nt = 0; nt < 4; ++nt)
            #pragma unroll
            for (int ci = 0; ci < 4; ++ci) qC[mt][nt][ci] = 0.f;
    gemm64(sA, sW, wm, wn, g, t4, qC);
    __syncthreads();            // sW reads done before restage

    for (int r = 0; r < 5; ++r) {
        stage_W(sW, 1 + r);
        if (r > 0) stage_A(sA, x, nbr, is64, n0, r, N);
        cpa_waitall();
        __syncthreads();

        float kC[2][4][4];
        #pragma unroll
        for (int mt = 0; mt < 2; ++mt)
            #pragma unroll
            for (int nt = 0; nt < 4; ++nt)
                #pragma unroll
                for (int ci = 0; ci < 4; ++ci) kC[mt][nt][ci] = 0.f;
        gemm64(sA, sW, wm, wn, g, t4, kC);

        // ---- logits, exp, E store, partial sums (head h = wn) ----
        float hs = 0.f;
        #pragma unroll
        for (int mt = 0; mt < 2; ++mt) {
            #pragma unroll
            for (int rr = 0; rr < 2; ++rr) {
                int n = n0 + wm * 32 + mt * 16 + g + rr * 8;
                float ds = 0.f;
                #pragma unroll
                for (int nt = 0; nt < 4; ++nt) {
                    ds = fmaf(qC[mt][nt][rr * 2],     kC[mt][nt][rr * 2],     ds);
                    ds = fmaf(qC[mt][nt][rr * 2 + 1], kC[mt][nt][rr * 2 + 1], ds);
                }
                ds += __shfl_xor_sync(0xFFFFFFFFu, ds, 1);
                ds += __shfl_xor_sync(0xFFFFFFFFu, ds, 2);
                if (t4 == 0) {
                    float e = 0.f;
                    if (n < N) {
                        e = expf(ds * SCALE);
                        g_E[(size_t)(h * 5 + r) * N + n] = e;
                    }
                    hs += e;
                }
            }
        }
        #pragma unroll
        for (int o = 16; o > 0; o >>= 1)
            hs += __shfl_down_sync(0xFFFFFFFFu, hs, o);
        if (l == 0) warr[w] = hs;
        __syncthreads();        // also guarantees GEMM smem reads done
        if (t < 4)
            g_part[(t * 5 + r) * MAXTILES + tile] = warr[t] + warr[4 + t];
    }
}

// -------- kernel R --------
__global__ void knot_R(int cnt)
{
    __shared__ float smr[256];
    const int b = blockIdx.x;
    float s = 0.f;
    for (int i = threadIdx.x; i < cnt; i += 256) s += g_part[b * MAXTILES + i];
    smr[threadIdx.x] = s;
    __syncthreads();
    for (int off = 128; off > 0; off >>= 1) {
        if (threadIdx.x < off) smr[threadIdx.x] += smr[threadIdx.x + off];
        __syncthreads();
    }
    if (threadIdx.x == 0) g_Sinv[b] = 1.0f / smr[0];
}

// -------- kernel O --------
__global__ __launch_bounds__(THREADS, 2)
void knot_O(const float* __restrict__ x, const void* __restrict__ nbr,
            float* __restrict__ out, int N)
{
    extern __shared__ float smf[];
    float* sA = smf;
    float* sW = smf + W_OFF;

    const int t = threadIdx.x, w = t >> 5, l = t & 31;
    const int wm = w >> 2, wn = w & 3, g = l >> 2, t4 = l & 3;
    const int tile = blockIdx.x, n0 = tile * NT;
    const int is64 = g_is64;
    const int h = wn;

    float acc[2][4][4];
    #pragma unroll
    for (int mt = 0; mt < 2; ++mt)
        #pragma unroll
        for (int nt = 0; nt < 4; ++nt)
            #pragma unroll
            for (int ci = 0; ci < 4; ++ci) acc[mt][nt][ci] = 0.f;

    for (int r = 0; r < 5; ++r) {
        stage_W(sW, 6 + r);
        stage_A(sA, x, nbr, is64, n0, r, N);
        cpa_waitall();
        __syncthreads();

        float C[2][4][4];
        #pragma unroll
        for (int mt = 0; mt < 2; ++mt)
            #pragma unroll
            for (int nt = 0; nt < 4; ++nt)
                #pragma unroll
                for (int ci = 0; ci < 4; ++ci) C[mt][nt][ci] = 0.f;
        gemm64(sA, sW, wm, wn, g, t4, C);

        float av[2][2];   // [mt][rr], head h
        const float si = g_Sinv[h * 5 + r];
        #pragma unroll
        for (int mt = 0; mt < 2; ++mt)
            #pragma unroll
            for (int rr = 0; rr < 2; ++rr) {
                int n = n0 + wm * 32 + mt * 16 + g + rr * 8;
                av[mt][rr] = (n < N)
                    ? __ldg(&g_E[(size_t)(h * 5 + r) * N + n]) * si : 0.f;
            }
        #pragma unroll
        for (int mt = 0; mt < 2; ++mt)
            #pragma unroll
            for (int nt = 0; nt < 4; ++nt)
                #pragma unroll
                for (int ci = 0; ci < 4; ++ci)
                    acc[mt][nt][ci] = fmaf(av[mt][ci >> 1], C[mt][nt][ci],
                                           acc[mt][nt][ci]);
        __syncthreads();    // smem reads done before next restage / transpose
    }

    // ---- transpose via smem (A region, 64 x AS), coalesced output ----
    #pragma unroll
    for (int mt = 0; mt < 2; ++mt)
        #pragma unroll
        for (int nt = 0; nt < 4; ++nt)
            #pragma unroll
            for (int ci = 0; ci < 4; ++ci) {
                int row = wm * 32 + mt * 16 + g + (ci >> 1) * 8;
                int col = wn * 32 + nt * 8 + t4 * 2 + (ci & 1);
                sA[row * AS + col] = acc[mt][nt][ci];
            }
    __syncthreads();
    #pragma unroll
    for (int i = 0; i < 8; ++i) {
        int f = t + 256 * i;
        int row = f >> 5, c4 = f & 31;
        int n = n0 + row;
        if (n < N)
            *(float4*)(out + (size_t)n * 128 + c4 * 4) =
                *(const float4*)(sA + row * AS + c4 * 4);
    }
}

extern "C" void kernel_launch(void* const* d_in, const int* in_sizes, int n_in,
                              void* d_out, int out_size)
{
    const float* x   = (const float*)d_in[0];
    const void*  nbr = d_in[1];
    const float* wq  = (const float*)d_in[2];
    const float* wk  = (const float*)d_in[3];
    const float* wv  = (const float*)d_in[4];
    float*       out = (float*)d_out;

    const int N   = in_sizes[0] / 128;
    const int NBT = (N + NT - 1) / NT;

    cudaFuncSetAttribute(knot_E, cudaFuncAttributeMaxDynamicSharedMemorySize, SMEM_SZ);
    cudaFuncSetAttribute(knot_O, cudaFuncAttributeMaxDynamicSharedMemorySize, SMEM_SZ);

    knot_detect<<<1, 32>>>((const int*)nbr);
    knot_prep<<<11, 256>>>(wq, wk, wv);
    knot_E<<<NBT, THREADS, SMEM_SZ>>>(x, nbr, N);
    knot_R<<<20, 256>>>(NBT);
    knot_O<<<NBT, THREADS, SMEM_SZ>>>(x, nbr, out, N);
}